// round 11
// baseline (speedup 1.0000x reference)
#include <cuda_runtime.h>
#include <cuda_fp16.h>
#include <cuda_fp8.h>
#include <math.h>
#include <stdint.h>

#define Bn 32
#define Tn 1024
#define Dn 512
#define Gn 256
#define En 8
#define Vn 8192

#define BM 128
#define BN 64
#define BK 64
#define GTHREADS 128
#define NTHREADS 256

#define L2E 1.4426950408889634f
#define LN2 0.6931471805599453f
#define WSCALE 64.0f

// smem strides (bytes), padded for conflict-free ldmatrix
#define A_STRIDE 80      // 64 fp8 = 64B + 16B pad
#define B_STRIDE 80      // 64 fp8 = 64B + 16B pad
#define A_BYTES (BM * A_STRIDE)          // 10240
#define B_BYTES (BN * B_STRIDE)          // 5120
#define STAGE_BYTES (A_BYTES + B_BYTES)  // 15360
#define NSTAGES 3
#define SM_MBAR (NSTAGES * STAGE_BYTES)  // 46080
#define SMEM_BYTES (SM_MBAR + 64)        // 46144 per CTA, 4 CTAs/SM

// ---------------- scratch (no cudaMalloc allowed) ----------------
__device__ unsigned char g_Xq[(size_t)Bn * Tn * Dn];   // [B,T,D] e4m3
__device__ unsigned char g_Wq[(size_t)En * Vn * Dn];   // [E,V,D] e4m3 (transposed, x64)
__device__ float g_sumexp[Bn * Tn];
__device__ float g_tgt[Bn * Tn];                // stores logit * log2(e)
__device__ int   g_assign[Bn];
__device__ float g_ce[Bn];

// ---------------- helpers ----------------
__device__ __forceinline__ uint32_t s2u(const void* p) {
    uint32_t a;
    asm("{ .reg .u64 t; cvta.to.shared.u64 t, %1; cvt.u32.u64 %0, t; }" : "=r"(a) : "l"(p));
    return a;
}
__device__ __forceinline__ void cp16(uint32_t dst, const void* src) {
    asm volatile("cp.async.cg.shared.global [%0], [%1], 16;" :: "r"(dst), "l"(src) : "memory");
}
__device__ __forceinline__ void mwait(uint32_t addr, uint32_t phase) {
    asm volatile(
        "{\n\t.reg .pred P;\n\t"
        "WL_%=:\n\t"
        "mbarrier.try_wait.parity.acquire.cta.shared::cta.b64 P, [%0], %1, 0x989680;\n\t"
        "@P bra WD_%=;\n\t"
        "bra WL_%=;\n\t"
        "WD_%=:\n\t}"
        :: "r"(addr), "r"(phase) : "memory");
}
__device__ __forceinline__ void mbar_init(uint32_t a, uint32_t cnt) {
    asm volatile("mbarrier.init.shared::cta.b64 [%0], %1;" :: "r"(a), "r"(cnt) : "memory");
}
__device__ __forceinline__ void mbar_arrive(uint32_t a) {
    asm volatile("mbarrier.arrive.shared::cta.b64 _, [%0];" :: "r"(a) : "memory");
}
__device__ __forceinline__ void cpasync_arrive(uint32_t a) {
    asm volatile("cp.async.mbarrier.arrive.noinc.shared::cta.b64 [%0];" :: "r"(a) : "memory");
}
__device__ __forceinline__ void ldsm_x4(uint32_t& r0, uint32_t& r1, uint32_t& r2, uint32_t& r3, uint32_t a) {
    asm volatile("ldmatrix.sync.aligned.m8n8.x4.shared.b16 {%0,%1,%2,%3}, [%4];"
                 : "=r"(r0), "=r"(r1), "=r"(r2), "=r"(r3) : "r"(a));
}
// fp8 e4m3 MMA, f32 accumulate (sm_89+ plain feature)
__device__ __forceinline__ void mma_e4m3(float* d, const uint32_t* a, uint32_t b0, uint32_t b1) {
    asm volatile("mma.sync.aligned.m16n8k32.row.col.f32.e4m3.e4m3.f32 "
                 "{%0,%1,%2,%3}, {%4,%5,%6,%7}, {%8,%9}, {%0,%1,%2,%3};"
                 : "+f"(d[0]), "+f"(d[1]), "+f"(d[2]), "+f"(d[3])
                 : "r"(a[0]), "r"(a[1]), "r"(a[2]), "r"(a[3]), "r"(b0), "r"(b1));
}
__device__ __forceinline__ float ex2f(float x) {
    float y; asm("ex2.approx.f32 %0, %1;" : "=f"(y) : "f"(x)); return y;
}
__device__ __forceinline__ uint32_t pack_e4m3x4(float a, float b, float c, float d) {
    __nv_fp8x2_storage_t lo = __nv_cvt_float2_to_fp8x2(make_float2(a, b), __NV_SATFINITE, __NV_E4M3);
    __nv_fp8x2_storage_t hi = __nv_cvt_float2_to_fp8x2(make_float2(c, d), __NV_SATFINITE, __NV_E4M3);
    return (uint32_t)lo | ((uint32_t)hi << 16);
}

// ---------------- conversion kernels ----------------
__global__ void convert_x_kernel(const float4* __restrict__ X) {
    size_t i = (size_t)blockIdx.x * blockDim.x + threadIdx.x;
    float4 v = X[i];
    ((uint32_t*)g_Xq)[i] = pack_e4m3x4(v.x, v.y, v.z, v.w);
}
// We[e][d][v] fp32 -> g_Wq[e][v][d] e4m3 * 64 (transpose via smem tile)
__global__ void convert_w_kernel(const float* __restrict__ We) {
    __shared__ float tile[32][33];
    const int tx = threadIdx.x & 31;
    const int ty = threadIdx.x >> 5;        // 0..7
    const int v0 = blockIdx.x * 32;
    const int d0 = blockIdx.y * 32;
    const int e  = blockIdx.z;
    #pragma unroll
    for (int i = 0; i < 4; i++) {
        int d = d0 + ty + i * 8;
        tile[ty + i * 8][tx] = We[((size_t)e * Dn + d) * Vn + v0 + tx];
    }
    __syncthreads();
    const int v  = threadIdx.x >> 3;          // 0..31
    const int dq = (threadIdx.x & 7) * 4;     // 0..28
    uint32_t p = pack_e4m3x4(tile[dq][v] * WSCALE, tile[dq + 1][v] * WSCALE,
                             tile[dq + 2][v] * WSCALE, tile[dq + 3][v] * WSCALE);
    ((uint32_t*)g_Wq)[(((size_t)e * Vn + v0 + v) * Dn + d0 + dq) >> 2] = p;
}

// ---------------- router ----------------
__global__ void router_kernel(const float* __restrict__ gate,
                              const float* __restrict__ Wg,
                              const float* __restrict__ bg,
                              float* __restrict__ out, int out_size)
{
    int tid = threadIdx.x;
    for (int i = tid; i < out_size; i += NTHREADS) out[i] = 0.0f;
    for (int i = tid; i < Bn * Tn; i += NTHREADS) g_sumexp[i] = 0.0f;

    __shared__ float logits[Bn][En];
    int i = tid / En, j = tid % En;
    float acc = bg[j];
    const float* grow = gate + i * Gn;
    #pragma unroll 4
    for (int g = 0; g < Gn; g++) acc += grow[g] * Wg[g * En + j];
    logits[i][j] = acc;
    __syncthreads();

    if (tid < Bn) {
        float mx = logits[tid][0];
        int am = 0;
        #pragma unroll
        for (int e = 1; e < En; e++) {
            float v = logits[tid][e];
            if (v > mx) { mx = v; am = e; }
        }
        float ex[En], s = 0.0f;
        #pragma unroll
        for (int e = 0; e < En; e++) { ex[e] = expf(logits[tid][e] - mx); s += ex[e]; }
        float inv = 1.0f / s;
        #pragma unroll
        for (int e = 0; e < En; e++) out[1 + Bn + tid * En + e] = ex[e] * inv;
        out[1 + tid] = (float)am;
        g_assign[tid] = am;
    }
}

// ---------------- fused FP8 MMA GEMM + CE epilogue ----------------
// grid (V/BN=128, T/BM=8, B=32), 128 threads, 4 warps 2(M)x2(N),
// warp tile 64x32, f32 acc, 4 CTAs/SM, mbarrier ring (no mainloop syncthreads).
__device__ __forceinline__ void load_stage(uint32_t sA, uint32_t sB,
                                           const unsigned char* Ag,
                                           const unsigned char* Bg,
                                           int k0, int tid)
{
    // A: 128 rows x 64B = 512 x 16B segs; 4 per thread
    #pragma unroll
    for (int i = 0; i < 4; i++) {
        int s = tid + i * GTHREADS;
        int row = s >> 2, j = s & 3;
        cp16(sA + (uint32_t)(row * A_STRIDE + j * 16),
             Ag + (size_t)row * Dn + k0 + j * 16);
    }
    // B: 64 v-rows x 64B = 256 x 16B segs; 2 per thread
    #pragma unroll
    for (int i = 0; i < 2; i++) {
        int s = tid + i * GTHREADS;
        int row = s >> 2, j = s & 3;
        cp16(sB + (uint32_t)(row * B_STRIDE + j * 16),
             Bg + (size_t)row * Dn + k0 + j * 16);
    }
}

__global__ void __launch_bounds__(GTHREADS, 4)
gemm_ce_kernel(const float* __restrict__ be, const int* __restrict__ tgt32)
{
    extern __shared__ char smem[];
    const uint32_t sbase = s2u(smem);
    const uint32_t mbase = sbase + SM_MBAR;   // full[s]=+s*16, free[s]=+s*16+8
    const int tid  = threadIdx.x;
    const int wid  = tid >> 5;
    const int lane = tid & 31;
    const int wm   = wid >> 1;    // 0..1 (64 rows)
    const int wn   = wid & 1;     // 0..1 (32 cols)

    const int vt = blockIdx.x, tt = blockIdx.y, b = blockIdx.z;
    const int e  = g_assign[b];
    const int v0 = vt * BN;
    const int t0 = tt * BM;

    const unsigned char* Ag = g_Xq + ((size_t)b * Tn + t0) * Dn;
    const unsigned char* Bg = g_Wq + ((size_t)e * Vn + v0) * Dn;

    if (tid == 0) {
        #pragma unroll
        for (int s = 0; s < NSTAGES; s++) {
            mbar_init(mbase + s * 16,     128);  // full
            mbar_init(mbase + s * 16 + 8, 4);    // free
        }
    }
    __syncthreads();

    float acc[4][4][4];
    #pragma unroll
    for (int mt = 0; mt < 4; mt++)
        #pragma unroll
        for (int nt = 0; nt < 4; nt++)
            #pragma unroll
            for (int r = 0; r < 4; r++) acc[mt][nt][r] = 0.0f;

    const uint32_t a_lane_off = (uint32_t)((lane & 15) * A_STRIDE + (lane >> 4) * 16)
                              + (uint32_t)(wm * 64 * A_STRIDE);
    const uint32_t b_lane_off = (uint32_t)((lane & 15) * B_STRIDE + (lane >> 4) * 16)
                              + (uint32_t)(wn * 32 * B_STRIDE);

    uint32_t prod_ph = 7u;
    uint32_t cons_ph = 0u;

    #pragma unroll
    for (int k = 0; k < 2; k++) {
        mwait(mbase + k * 16 + 8, (prod_ph >> k) & 1u);
        prod_ph ^= (1u << k);
        load_stage(sbase + k * STAGE_BYTES, sbase + k * STAGE_BYTES + A_BYTES,
                   Ag, Bg, k * BK, tid);
        cpasync_arrive(mbase + k * 16);
    }

    const int NCHUNK = Dn / BK;   // 8
    int ps = 2, cs = 0;
    #pragma unroll 1
    for (int c = 0; c < NCHUNK; c++) {
        if (c + 2 < NCHUNK) {
            mwait(mbase + ps * 16 + 8, (prod_ph >> ps) & 1u);
            prod_ph ^= (1u << ps);
            load_stage(sbase + ps * STAGE_BYTES, sbase + ps * STAGE_BYTES + A_BYTES,
                       Ag, Bg, (c + 2) * BK, tid);
            cpasync_arrive(mbase + ps * 16);
            if (++ps == NSTAGES) ps = 0;
        }

        mwait(mbase + cs * 16, (cons_ph >> cs) & 1u);
        cons_ph ^= (1u << cs);

        const uint32_t aBase = sbase + cs * STAGE_BYTES + a_lane_off;
        const uint32_t bBase = sbase + cs * STAGE_BYTES + A_BYTES + b_lane_off;

        #pragma unroll
        for (int kt = 0; kt < 2; kt++) {   // two k32 steps per BK=64 chunk
            uint32_t af[4][4], bf[2][4];
            #pragma unroll
            for (int mt = 0; mt < 4; mt++)
                ldsm_x4(af[mt][0], af[mt][1], af[mt][2], af[mt][3],
                        aBase + (uint32_t)(mt * 16 * A_STRIDE + kt * 32));
            // B non-trans x4 over n16 x k32: mats = {b0(nt=2g), b0(2g+1), b1(2g), b1(2g+1)}
            #pragma unroll
            for (int g = 0; g < 2; g++)
                ldsm_x4(bf[g][0], bf[g][1], bf[g][2], bf[g][3],
                        bBase + (uint32_t)(g * 16 * B_STRIDE + kt * 32));
            #pragma unroll
            for (int mt = 0; mt < 4; mt++)
                #pragma unroll
                for (int nt = 0; nt < 4; nt++)
                    mma_e4m3(acc[mt][nt], af[mt], bf[nt >> 1][nt & 1], bf[nt >> 1][(nt & 1) + 2]);
        }

        __syncwarp();
        if (lane == 0) mbar_arrive(mbase + cs * 16 + 8);
        if (++cs == NSTAGES) cs = 0;
    }

    // ---- epilogue: t = logit*log2e; exp via ex2.approx.f32; unscale W x64 ----
    const int c0 = (lane & 3) * 2;
    const int r0 = lane >> 2;
    const int vbase = v0 + wn * 32 + c0;
    const float* bias_base = be + (size_t)e * Vn + vbase;
    const float s1 = L2E / WSCALE;

    float bl[4], bh[4];
    #pragma unroll
    for (int nt = 0; nt < 4; nt++) {
        bl[nt] = bias_base[nt * 8] * L2E;
        bh[nt] = bias_base[nt * 8 + 1] * L2E;
    }

    #pragma unroll
    for (int mt = 0; mt < 4; mt++) {
        const int row0 = t0 + wm * 64 + mt * 16 + r0;
        const int row1 = row0 + 8;
        const int d0 = tgt32[2 * (b * Tn + row0)] - vbase;   // int64 targets, low word
        const int d1 = tgt32[2 * (b * Tn + row1)] - vbase;
        float su0 = 0.0f, su1 = 0.0f;
        #pragma unroll
        for (int nt = 0; nt < 4; nt++) {
            float t00 = fmaf(acc[mt][nt][0], s1, bl[nt]);
            float t01 = fmaf(acc[mt][nt][1], s1, bh[nt]);
            float t10 = fmaf(acc[mt][nt][2], s1, bl[nt]);
            float t11 = fmaf(acc[mt][nt][3], s1, bh[nt]);
            su0 += ex2f(t00) + ex2f(t01);
            su1 += ex2f(t10) + ex2f(t11);
            if (d0 == nt * 8)     g_tgt[(size_t)b * Tn + row0] = t00;
            if (d0 == nt * 8 + 1) g_tgt[(size_t)b * Tn + row0] = t01;
            if (d1 == nt * 8)     g_tgt[(size_t)b * Tn + row1] = t10;
            if (d1 == nt * 8 + 1) g_tgt[(size_t)b * Tn + row1] = t11;
        }
        su0 += __shfl_xor_sync(0xffffffffu, su0, 1);
        su0 += __shfl_xor_sync(0xffffffffu, su0, 2);
        su1 += __shfl_xor_sync(0xffffffffu, su1, 1);
        su1 += __shfl_xor_sync(0xffffffffu, su1, 2);
        if ((lane & 3) == 0) {
            atomicAdd(&g_sumexp[(size_t)b * Tn + row0], su0);
            atomicAdd(&g_sumexp[(size_t)b * Tn + row1], su1);
        }
    }
}

// ---------------- CE reductions ----------------
__global__ void ce_reduce_kernel()
{
    const int b = blockIdx.x;
    const int tid = threadIdx.x;
    float s = 0.0f;
    for (int t = tid; t < Tn; t += NTHREADS) {
        const int idx = b * Tn + t;
        s += logf(g_sumexp[idx]) - g_tgt[idx] * LN2;   // g_tgt holds logit*log2e
    }
    __shared__ float red[NTHREADS];
    red[tid] = s;
    __syncthreads();
    for (int off = NTHREADS / 2; off > 0; off >>= 1) {
        if (tid < off) red[tid] += red[tid + off];
        __syncthreads();
    }
    if (tid == 0) g_ce[b] = red[0] / (float)Tn;
}

__global__ void final_kernel(float* __restrict__ out)
{
    if (threadIdx.x == 0) {
        float sums[En], cnt[En];
        #pragma unroll
        for (int e = 0; e < En; e++) { sums[e] = 0.0f; cnt[e] = 0.0f; }
        for (int b = 0; b < Bn; b++) {
            sums[g_assign[b]] += g_ce[b];
            cnt[g_assign[b]]  += 1.0f;
        }
        float tot = 0.0f;
        #pragma unroll
        for (int e = 0; e < En; e++)
            if (cnt[e] > 0.0f) tot += sums[e] / cnt[e];
        out[0] = tot;
    }
}

// ---------------- launcher ----------------
extern "C" void kernel_launch(void* const* d_in, const int* in_sizes, int n_in,
                              void* d_out, int out_size)
{
    const float* gate = (const float*)d_in[0];
    const float* X    = (const float*)d_in[1];
    const float* Wg   = (const float*)d_in[2];
    const float* bg   = (const float*)d_in[3];
    const float* We   = (const float*)d_in[4];
    const float* be   = (const float*)d_in[5];
    const int*   tgt  = (const int*)d_in[6];
    float* out = (float*)d_out;

    cudaFuncSetAttribute(gemm_ce_kernel, cudaFuncAttributeMaxDynamicSharedMemorySize, SMEM_BYTES);

    convert_x_kernel<<<((size_t)Bn * Tn * Dn / 4) / 256, 256>>>((const float4*)X);
    dim3 wgrid(Vn / 32, Dn / 32, En);
    convert_w_kernel<<<wgrid, 256>>>(We);

    router_kernel<<<1, NTHREADS>>>(gate, Wg, bg, out, out_size);

    dim3 grid(Vn / BN, Tn / BM, Bn);
    gemm_ce_kernel<<<grid, GTHREADS, SMEM_BYTES>>>(be, tgt);

    ce_reduce_kernel<<<Bn, NTHREADS>>>();
    final_kernel<<<1, 32>>>(out);
}

// round 12
// speedup vs baseline: 1.1067x; 1.1067x over previous
#include <cuda_runtime.h>
#include <cuda_fp16.h>
#include <math.h>
#include <stdint.h>

#define Bn 32
#define Tn 1024
#define Dn 512
#define Gn 256
#define En 8
#define Vn 8192

#define BM 128
#define BN 128
#define BK 32
#define GTHREADS 128
#define NTHREADS 256

#define L2E 1.4426950408889634f
#define LN2 0.6931471805599453f

// smem strides (bytes), padded for conflict-free ldmatrix
#define A_STRIDE 80      // 32 f16 = 64B + 16B pad
#define B_STRIDE 272     // 128 f16 = 256B + 16B pad
#define A_BYTES (BM * A_STRIDE)          // 10240
#define B_BYTES (BK * B_STRIDE)          // 8704
#define STAGE_BYTES (A_BYTES + B_BYTES)  // 18944
#define NSTAGES 3
#define SM_MBAR (NSTAGES * STAGE_BYTES)  // 56832
#define SMEM_BYTES (SM_MBAR + 64)        // 56896 per CTA, 3 CTAs/SM

// ---------------- scratch (no cudaMalloc allowed) ----------------
__device__ __half g_Xh[(size_t)Bn * Tn * Dn];   // [B,T,D]
__device__ __half g_Wh[(size_t)En * Dn * Vn];   // [E,D,V]
__device__ float g_sumexp[Bn * Tn];
__device__ float g_tgt[Bn * Tn];                // stores logit * log2(e)
__device__ int   g_assign[Bn];
__device__ float g_ce[Bn];

// ---------------- helpers ----------------
__device__ __forceinline__ uint32_t s2u(const void* p) {
    uint32_t a;
    asm("{ .reg .u64 t; cvta.to.shared.u64 t, %1; cvt.u32.u64 %0, t; }" : "=r"(a) : "l"(p));
    return a;
}
__device__ __forceinline__ void cp16(uint32_t dst, const void* src) {
    asm volatile("cp.async.cg.shared.global [%0], [%1], 16;" :: "r"(dst), "l"(src) : "memory");
}
__device__ __forceinline__ void mwait(uint32_t addr, uint32_t phase) {
    asm volatile(
        "{\n\t.reg .pred P;\n\t"
        "WL_%=:\n\t"
        "mbarrier.try_wait.parity.acquire.cta.shared::cta.b64 P, [%0], %1, 0x989680;\n\t"
        "@P bra WD_%=;\n\t"
        "bra WL_%=;\n\t"
        "WD_%=:\n\t}"
        :: "r"(addr), "r"(phase) : "memory");
}
__device__ __forceinline__ void mbar_init(uint32_t a, uint32_t cnt) {
    asm volatile("mbarrier.init.shared::cta.b64 [%0], %1;" :: "r"(a), "r"(cnt) : "memory");
}
__device__ __forceinline__ void mbar_arrive(uint32_t a) {
    asm volatile("mbarrier.arrive.shared::cta.b64 _, [%0];" :: "r"(a) : "memory");
}
__device__ __forceinline__ void cpasync_arrive(uint32_t a) {
    asm volatile("cp.async.mbarrier.arrive.noinc.shared::cta.b64 [%0];" :: "r"(a) : "memory");
}
__device__ __forceinline__ void ldsm_x4(uint32_t& r0, uint32_t& r1, uint32_t& r2, uint32_t& r3, uint32_t a) {
    asm volatile("ldmatrix.sync.aligned.m8n8.x4.shared.b16 {%0,%1,%2,%3}, [%4];"
                 : "=r"(r0), "=r"(r1), "=r"(r2), "=r"(r3) : "r"(a));
}
__device__ __forceinline__ void ldsm_x4t(uint32_t& r0, uint32_t& r1, uint32_t& r2, uint32_t& r3, uint32_t a) {
    asm volatile("ldmatrix.sync.aligned.m8n8.x4.trans.shared.b16 {%0,%1,%2,%3}, [%4];"
                 : "=r"(r0), "=r"(r1), "=r"(r2), "=r"(r3) : "r"(a));
}
__device__ __forceinline__ void mma_f16(uint32_t* d, const uint32_t* a, const uint32_t* b) {
    asm volatile("mma.sync.aligned.m16n8k16.row.col.f16.f16.f16.f16 "
                 "{%0,%1}, {%2,%3,%4,%5}, {%6,%7}, {%0,%1};"
                 : "+r"(d[0]), "+r"(d[1])
                 : "r"(a[0]), "r"(a[1]), "r"(a[2]), "r"(a[3]), "r"(b[0]), "r"(b[1]));
}
__device__ __forceinline__ __half2 h2ex2(__half2 x) {
    __half2 r;
    asm("ex2.approx.f16x2 %0, %1;" : "=r"(*(uint32_t*)&r) : "r"(*(uint32_t*)&x));
    return r;
}

// ---------------- conversion kernels (fp32 -> f16) ----------------
__global__ void convert_x_kernel(const float4* __restrict__ X) {
    size_t i = (size_t)blockIdx.x * blockDim.x + threadIdx.x;
    float4 v = X[i];
    __half2* o = (__half2*)g_Xh;
    o[2 * i + 0] = __floats2half2_rn(v.x, v.y);
    o[2 * i + 1] = __floats2half2_rn(v.z, v.w);
}
__global__ void convert_w_kernel(const float4* __restrict__ W) {
    size_t i = (size_t)blockIdx.x * blockDim.x + threadIdx.x;
    float4 v = W[i];
    __half2* o = (__half2*)g_Wh;
    o[2 * i + 0] = __floats2half2_rn(v.x, v.y);
    o[2 * i + 1] = __floats2half2_rn(v.z, v.w);
}

// ---------------- router ----------------
__global__ void router_kernel(const float* __restrict__ gate,
                              const float* __restrict__ Wg,
                              const float* __restrict__ bg,
                              float* __restrict__ out, int out_size)
{
    int tid = threadIdx.x;
    for (int i = tid; i < out_size; i += NTHREADS) out[i] = 0.0f;
    for (int i = tid; i < Bn * Tn; i += NTHREADS) g_sumexp[i] = 0.0f;

    __shared__ float logits[Bn][En];
    int i = tid / En, j = tid % En;
    float acc = bg[j];
    const float* grow = gate + i * Gn;
    #pragma unroll 4
    for (int g = 0; g < Gn; g++) acc += grow[g] * Wg[g * En + j];
    logits[i][j] = acc;
    __syncthreads();

    if (tid < Bn) {
        float mx = logits[tid][0];
        int am = 0;
        #pragma unroll
        for (int e = 1; e < En; e++) {
            float v = logits[tid][e];
            if (v > mx) { mx = v; am = e; }
        }
        float ex[En], s = 0.0f;
        #pragma unroll
        for (int e = 0; e < En; e++) { ex[e] = expf(logits[tid][e] - mx); s += ex[e]; }
        float inv = 1.0f / s;
        #pragma unroll
        for (int e = 0; e < En; e++) out[1 + Bn + tid * En + e] = ex[e] * inv;
        out[1 + tid] = (float)am;
        g_assign[tid] = am;
    }
}

// ---------------- fused HMMA GEMM + CE epilogue ----------------
// grid (V/BN=64, T/BM=8, B=32), 128 threads, 4 warps 2(M)x2(N), warp tile
// 64x64 f16 acc, 3 CTAs/SM. mbarrier ring + register-double-buffered
// fragments: LDSM of the next kt overlaps the MMAs of the current one.
__device__ __forceinline__ void load_stage(uint32_t sA, uint32_t sB,
                                           const __half* Ag,
                                           const __half* Bg,
                                           int k0, int tid)
{
    #pragma unroll
    for (int i = 0; i < 4; i++) {
        int s = tid + i * GTHREADS;
        int row = s >> 2, j = s & 3;
        cp16(sA + (uint32_t)(row * A_STRIDE + j * 16),
             Ag + (size_t)row * Dn + k0 + j * 8);
    }
    #pragma unroll
    for (int i = 0; i < 4; i++) {
        int s = tid + i * GTHREADS;
        int kr = s >> 4, j = s & 15;
        cp16(sB + (uint32_t)(kr * B_STRIDE + j * 16),
             Bg + (size_t)(k0 + kr) * Vn + j * 8);
    }
}

__global__ void __launch_bounds__(GTHREADS, 3)
gemm_ce_kernel(const float* __restrict__ be, const int* __restrict__ tgt32)
{
    extern __shared__ char smem[];
    const uint32_t sbase = s2u(smem);
    const uint32_t mbase = sbase + SM_MBAR;   // full[s]=+s*16, free[s]=+s*16+8
    const int tid  = threadIdx.x;
    const int wid  = tid >> 5;
    const int lane = tid & 31;
    const int wm   = wid >> 1;    // 0..1 (64 rows)
    const int wn   = wid & 1;     // 0..1 (64 cols)

    const int vt = blockIdx.x, tt = blockIdx.y, b = blockIdx.z;
    const int e  = g_assign[b];
    const int v0 = vt * BN;
    const int t0 = tt * BM;

    const __half* Ag = g_Xh + ((size_t)b * Tn + t0) * Dn;
    const __half* Bg = g_Wh + (size_t)e * Dn * Vn + v0;

    if (tid == 0) {
        #pragma unroll
        for (int s = 0; s < NSTAGES; s++) {
            mbar_init(mbase + s * 16,     128);  // full: per-thread cp.async arrive
            mbar_init(mbase + s * 16 + 8, 4);    // free: one arrive per warp
        }
    }
    __syncthreads();

    uint32_t acc[4][8][2];
    #pragma unroll
    for (int mt = 0; mt < 4; mt++)
        #pragma unroll
        for (int nt = 0; nt < 8; nt++) { acc[mt][nt][0] = 0u; acc[mt][nt][1] = 0u; }

    const uint32_t a_lane_off = (uint32_t)((lane & 15) * A_STRIDE + (lane >> 4) * 16)
                              + (uint32_t)(wm * 64 * A_STRIDE);
    const uint32_t b_lane_off = (uint32_t)((lane & 15) * B_STRIDE
                              + (wn * 64 + (lane >> 4) * 8) * 2);

    // fragment double buffers
    uint32_t af[2][16], bf[2][16];

    #define LDSM_FRAGS(buf, stgbase, kt) do {                                     \
        uint32_t _aB = (stgbase) + a_lane_off + (uint32_t)((kt) * 32);            \
        uint32_t _bB = (stgbase) + A_BYTES + b_lane_off                           \
                     + (uint32_t)((kt) * 16 * B_STRIDE);                          \
        _Pragma("unroll")                                                         \
        for (int _mt = 0; _mt < 4; _mt++)                                         \
            ldsm_x4(af[buf][_mt*4+0], af[buf][_mt*4+1],                           \
                    af[buf][_mt*4+2], af[buf][_mt*4+3],                           \
                    _aB + (uint32_t)(_mt * 16 * A_STRIDE));                       \
        _Pragma("unroll")                                                         \
        for (int _g = 0; _g < 4; _g++)                                            \
            ldsm_x4t(bf[buf][_g*4+0], bf[buf][_g*4+1],                            \
                     bf[buf][_g*4+2], bf[buf][_g*4+3],                            \
                     _bB + (uint32_t)(_g * 32));                                  \
    } while (0)

    #define MMA_BLOCK(buf) do {                                                   \
        _Pragma("unroll")                                                         \
        for (int _mt = 0; _mt < 4; _mt++)                                         \
            _Pragma("unroll")                                                     \
            for (int _nt = 0; _nt < 8; _nt++)                                     \
                mma_f16(acc[_mt][_nt], &af[buf][_mt*4], &bf[buf][_nt*2]);         \
    } while (0)

    uint32_t prod_ph = 7u;   // producers start at parity 1
    uint32_t cons_ph = 0u;   // consumers start at parity 0

    // producer prologue: chunks 0,1 -> stages 0,1
    #pragma unroll
    for (int k = 0; k < 2; k++) {
        mwait(mbase + k * 16 + 8, (prod_ph >> k) & 1u);
        prod_ph ^= (1u << k);
        load_stage(sbase + k * STAGE_BYTES, sbase + k * STAGE_BYTES + A_BYTES,
                   Ag, Bg, k * BK, tid);
        cpasync_arrive(mbase + k * 16);
    }

    // consumer prologue: (c0, kt0) -> buf0
    mwait(mbase + 0, 0);
    cons_ph ^= 1u;
    LDSM_FRAGS(0, sbase, 0);

    const int NCHUNK = Dn / BK;   // 16
    int cs = 0;                    // stage of current chunk
    #pragma unroll 1
    for (int c = 0; c < NCHUNK; c++) {
        const uint32_t stg = sbase + cs * STAGE_BYTES;

        // prefetch (c, kt1) -> buf1; stage fully read afterwards -> free it
        LDSM_FRAGS(1, stg, 1);
        __syncwarp();
        if (lane == 0) mbar_arrive(mbase + cs * 16 + 8);

        // MMAs for kt0 (buf0)
        MMA_BLOCK(0);

        int ns = cs + 1; if (ns == NSTAGES) ns = 0;

        // prefetch (c+1, kt0) -> buf0
        if (c + 1 < NCHUNK) {
            mwait(mbase + ns * 16, (cons_ph >> ns) & 1u);
            cons_ph ^= (1u << ns);
            LDSM_FRAGS(0, sbase + ns * STAGE_BYTES, 0);
        }

        // producer: chunk c+2 into its stage (== stage freed at chunk c-1)
        if (c + 2 < NCHUNK) {
            int ps = cs + 2; if (ps >= NSTAGES) ps -= NSTAGES;
            mwait(mbase + ps * 16 + 8, (prod_ph >> ps) & 1u);
            prod_ph ^= (1u << ps);
            load_stage(sbase + ps * STAGE_BYTES, sbase + ps * STAGE_BYTES + A_BYTES,
                       Ag, Bg, (c + 2) * BK, tid);
            cpasync_arrive(mbase + ps * 16);
        }

        // MMAs for kt1 (buf1)
        MMA_BLOCK(1);

        cs = ns;
    }

    // ---- epilogue: t = logit*log2e in half2; exp via ex2.f16x2 ----
    const int c0 = (lane & 3) * 2;
    const int r0 = lane >> 2;
    const int vbase = v0 + wn * 64 + c0;
    const float* bias_base = be + (size_t)e * Vn + vbase;

    const __half2 l2e = __float2half2_rn(L2E);

    #pragma unroll
    for (int mt = 0; mt < 4; mt++) {
        const int row0 = t0 + wm * 64 + mt * 16 + r0;
        const int row1 = row0 + 8;
        const int d0 = tgt32[2 * (b * Tn + row0)] - vbase;   // int64 targets, low word
        const int d1 = tgt32[2 * (b * Tn + row1)] - vbase;
        float s0 = 0.0f, s1 = 0.0f;
        #pragma unroll
        for (int nt = 0; nt < 8; nt++) {
            __half2 bsc = __floats2half2_rn(bias_base[nt * 8] * L2E,
                                            bias_base[nt * 8 + 1] * L2E);
            __half2 a0 = *(__half2*)&acc[mt][nt][0];
            __half2 a1 = *(__half2*)&acc[mt][nt][1];
            __half2 t0h = __hfma2(a0, l2e, bsc);
            __half2 t1h = __hfma2(a1, l2e, bsc);
            float2 e0 = __half22float2(h2ex2(t0h));
            float2 e1 = __half22float2(h2ex2(t1h));
            s0 += e0.x + e0.y;
            s1 += e1.x + e1.y;
            if (d0 == nt * 8)     g_tgt[(size_t)b * Tn + row0] = __low2float(t0h);
            if (d0 == nt * 8 + 1) g_tgt[(size_t)b * Tn + row0] = __high2float(t0h);
            if (d1 == nt * 8)     g_tgt[(size_t)b * Tn + row1] = __low2float(t1h);
            if (d1 == nt * 8 + 1) g_tgt[(size_t)b * Tn + row1] = __high2float(t1h);
        }
        s0 += __shfl_xor_sync(0xffffffffu, s0, 1);
        s0 += __shfl_xor_sync(0xffffffffu, s0, 2);
        s1 += __shfl_xor_sync(0xffffffffu, s1, 1);
        s1 += __shfl_xor_sync(0xffffffffu, s1, 2);
        if ((lane & 3) == 0) {
            atomicAdd(&g_sumexp[(size_t)b * Tn + row0], s0);
            atomicAdd(&g_sumexp[(size_t)b * Tn + row1], s1);
        }
    }
}

// ---------------- CE reductions ----------------
__global__ void ce_reduce_kernel()
{
    const int b = blockIdx.x;
    const int tid = threadIdx.x;
    float s = 0.0f;
    for (int t = tid; t < Tn; t += NTHREADS) {
        const int idx = b * Tn + t;
        s += logf(g_sumexp[idx]) - g_tgt[idx] * LN2;   // g_tgt holds logit*log2e
    }
    __shared__ float red[NTHREADS];
    red[tid] = s;
    __syncthreads();
    for (int off = NTHREADS / 2; off > 0; off >>= 1) {
        if (tid < off) red[tid] += red[tid + off];
        __syncthreads();
    }
    if (tid == 0) g_ce[b] = red[0] / (float)Tn;
}

__global__ void final_kernel(float* __restrict__ out)
{
    if (threadIdx.x == 0) {
        float sums[En], cnt[En];
        #pragma unroll
        for (int e = 0; e < En; e++) { sums[e] = 0.0f; cnt[e] = 0.0f; }
        for (int b = 0; b < Bn; b++) {
            sums[g_assign[b]] += g_ce[b];
            cnt[g_assign[b]]  += 1.0f;
        }
        float tot = 0.0f;
        #pragma unroll
        for (int e = 0; e < En; e++)
            if (cnt[e] > 0.0f) tot += sums[e] / cnt[e];
        out[0] = tot;
    }
}

// ---------------- launcher ----------------
extern "C" void kernel_launch(void* const* d_in, const int* in_sizes, int n_in,
                              void* d_out, int out_size)
{
    const float* gate = (const float*)d_in[0];
    const float* X    = (const float*)d_in[1];
    const float* Wg   = (const float*)d_in[2];
    const float* bg   = (const float*)d_in[3];
    const float* We   = (const float*)d_in[4];
    const float* be   = (const float*)d_in[5];
    const int*   tgt  = (const int*)d_in[6];
    float* out = (float*)d_out;

    cudaFuncSetAttribute(gemm_ce_kernel, cudaFuncAttributeMaxDynamicSharedMemorySize, SMEM_BYTES);

    convert_x_kernel<<<((size_t)Bn * Tn * Dn / 4) / 256, 256>>>((const float4*)X);
    convert_w_kernel<<<((size_t)En * Dn * Vn / 4) / 256, 256>>>((const float4*)We);

    router_kernel<<<1, NTHREADS>>>(gate, Wg, bg, out, out_size);

    dim3 grid(Vn / BN, Tn / BM, Bn);
    gemm_ce_kernel<<<grid, GTHREADS, SMEM_BYTES>>>(be, tgt);

    ce_reduce_kernel<<<Bn, NTHREADS>>>();
    final_kernel<<<1, 32>>>(out);
}

// round 13
// speedup vs baseline: 1.3001x; 1.1748x over previous
#include <cuda_runtime.h>
#include <cuda_fp16.h>
#include <math.h>
#include <stdint.h>

#define Bn 32
#define Tn 1024
#define Dn 512
#define Gn 256
#define En 8
#define Vn 8192

#define BM 128
#define BN 128
#define BK 32
#define GTHREADS 128
#define NTHREADS 256

#define L2E 1.4426950408889634f
#define LN2 0.6931471805599453f

// smem strides (bytes), padded for conflict-free ldmatrix
#define A_STRIDE 80      // 32 f16 = 64B + 16B pad
#define B_STRIDE 272     // 128 f16 = 256B + 16B pad
#define A_BYTES (BM * A_STRIDE)          // 10240
#define B_BYTES (BK * B_STRIDE)          // 8704
#define STAGE_BYTES (A_BYTES + B_BYTES)  // 18944
#define NSTAGES 3
#define SM_MBAR (NSTAGES * STAGE_BYTES)  // 56832
#define SMEM_BYTES (SM_MBAR + 64)        // 56896 per CTA, 4 CTAs/SM

// prep kernel block ranges
#define NB_X 16384          // X: 16.8M elems / 4 per thread / 256 thr
#define NB_W 32768          // W: 33.6M elems / 4 per thread / 256 thr
#define NB_Z 32             // zero g_sumexp (32768 floats)
#define NB_TOTAL (NB_X + NB_W + NB_Z + 1)

// ---------------- scratch (no cudaMalloc allowed) ----------------
__device__ __half g_Xh[(size_t)Bn * Tn * Dn];   // [B,T,D]
__device__ __half g_Wh[(size_t)En * Dn * Vn];   // [E,D,V]
__device__ float g_sumexp[Bn * Tn];
__device__ float g_tgt[Bn * Tn];                // stores logit * log2(e)
__device__ int   g_assign[Bn];
__device__ float g_ce[Bn];
__device__ int   g_cnt;

// ---------------- helpers ----------------
__device__ __forceinline__ uint32_t s2u(const void* p) {
    uint32_t a;
    asm("{ .reg .u64 t; cvta.to.shared.u64 t, %1; cvt.u32.u64 %0, t; }" : "=r"(a) : "l"(p));
    return a;
}
__device__ __forceinline__ void cp16(uint32_t dst, const void* src) {
    asm volatile("cp.async.cg.shared.global [%0], [%1], 16;" :: "r"(dst), "l"(src) : "memory");
}
__device__ __forceinline__ void mwait(uint32_t addr, uint32_t phase) {
    asm volatile(
        "{\n\t.reg .pred P;\n\t"
        "WL_%=:\n\t"
        "mbarrier.try_wait.parity.acquire.cta.shared::cta.b64 P, [%0], %1, 0x989680;\n\t"
        "@P bra WD_%=;\n\t"
        "bra WL_%=;\n\t"
        "WD_%=:\n\t}"
        :: "r"(addr), "r"(phase) : "memory");
}
__device__ __forceinline__ void mbar_init(uint32_t a, uint32_t cnt) {
    asm volatile("mbarrier.init.shared::cta.b64 [%0], %1;" :: "r"(a), "r"(cnt) : "memory");
}
__device__ __forceinline__ void mbar_arrive(uint32_t a) {
    asm volatile("mbarrier.arrive.shared::cta.b64 _, [%0];" :: "r"(a) : "memory");
}
__device__ __forceinline__ void cpasync_arrive(uint32_t a) {
    asm volatile("cp.async.mbarrier.arrive.noinc.shared::cta.b64 [%0];" :: "r"(a) : "memory");
}
__device__ __forceinline__ void ldsm_x4(uint32_t& r0, uint32_t& r1, uint32_t& r2, uint32_t& r3, uint32_t a) {
    asm volatile("ldmatrix.sync.aligned.m8n8.x4.shared.b16 {%0,%1,%2,%3}, [%4];"
                 : "=r"(r0), "=r"(r1), "=r"(r2), "=r"(r3) : "r"(a));
}
__device__ __forceinline__ void ldsm_x4t(uint32_t& r0, uint32_t& r1, uint32_t& r2, uint32_t& r3, uint32_t a) {
    asm volatile("ldmatrix.sync.aligned.m8n8.x4.trans.shared.b16 {%0,%1,%2,%3}, [%4];"
                 : "=r"(r0), "=r"(r1), "=r"(r2), "=r"(r3) : "r"(a));
}
__device__ __forceinline__ void mma_f16(uint32_t* d, const uint32_t* a, const uint32_t* b) {
    asm volatile("mma.sync.aligned.m16n8k16.row.col.f16.f16.f16.f16 "
                 "{%0,%1}, {%2,%3,%4,%5}, {%6,%7}, {%0,%1};"
                 : "+r"(d[0]), "+r"(d[1])
                 : "r"(a[0]), "r"(a[1]), "r"(a[2]), "r"(a[3]), "r"(b[0]), "r"(b[1]));
}
__device__ __forceinline__ __half2 h2ex2(__half2 x) {
    __half2 r;
    asm("ex2.approx.f16x2 %0, %1;" : "=r"(*(uint32_t*)&r) : "r"(*(uint32_t*)&x));
    return r;
}

// ---------------- prep: converts + zeroing + router, one kernel ----------------
__global__ void prep_kernel(const float4* __restrict__ X,
                            const float4* __restrict__ W,
                            const float* __restrict__ gate,
                            const float* __restrict__ Wg,
                            const float* __restrict__ bg,
                            float* __restrict__ out, int out_size)
{
    const int bid = blockIdx.x;
    const int tid = threadIdx.x;

    if (bid < NB_X) {
        size_t i = (size_t)bid * 256 + tid;
        float4 v = X[i];
        __half2* o = (__half2*)g_Xh;
        o[2 * i + 0] = __floats2half2_rn(v.x, v.y);
        o[2 * i + 1] = __floats2half2_rn(v.z, v.w);
        return;
    }
    if (bid < NB_X + NB_W) {
        size_t i = (size_t)(bid - NB_X) * 256 + tid;
        float4 v = W[i];
        __half2* o = (__half2*)g_Wh;
        o[2 * i + 0] = __floats2half2_rn(v.x, v.y);
        o[2 * i + 1] = __floats2half2_rn(v.z, v.w);
        return;
    }
    if (bid < NB_X + NB_W + NB_Z) {
        int i = (bid - NB_X - NB_W) * 1024 + tid * 4;
        *(float4*)&g_sumexp[i] = make_float4(0.f, 0.f, 0.f, 0.f);
        return;
    }

    // ---- router block ----
    for (int i = tid; i < out_size; i += NTHREADS) out[i] = 0.0f;
    if (tid == 0) g_cnt = 0;

    __shared__ float logits[Bn][En];
    int i = tid / En, j = tid % En;
    float acc = bg[j];
    const float* grow = gate + i * Gn;
    #pragma unroll 4
    for (int g = 0; g < Gn; g++) acc += grow[g] * Wg[g * En + j];
    logits[i][j] = acc;
    __syncthreads();

    if (tid < Bn) {
        float mx = logits[tid][0];
        int am = 0;
        #pragma unroll
        for (int e = 1; e < En; e++) {
            float v = logits[tid][e];
            if (v > mx) { mx = v; am = e; }
        }
        float ex[En], s = 0.0f;
        #pragma unroll
        for (int e = 0; e < En; e++) { ex[e] = expf(logits[tid][e] - mx); s += ex[e]; }
        float inv = 1.0f / s;
        #pragma unroll
        for (int e = 0; e < En; e++) out[1 + Bn + tid * En + e] = ex[e] * inv;
        out[1 + tid] = (float)am;
        g_assign[tid] = am;
    }
}

// ---------------- fused HMMA GEMM + CE epilogue (R10 shape) ----------------
// grid (V/BN=64, T/BM=8, B=32), 128 threads, 4 warps 2(M)x2(N),
// warp tile 64x64 f16 acc, 4 CTAs/SM, mbarrier ring pipeline.
__device__ __forceinline__ void load_stage(uint32_t sA, uint32_t sB,
                                           const __half* Ag,
                                           const __half* Bg,
                                           int k0, int tid)
{
    #pragma unroll
    for (int i = 0; i < 4; i++) {
        int s = tid + i * GTHREADS;
        int row = s >> 2, j = s & 3;
        cp16(sA + (uint32_t)(row * A_STRIDE + j * 16),
             Ag + (size_t)row * Dn + k0 + j * 8);
    }
    #pragma unroll
    for (int i = 0; i < 4; i++) {
        int s = tid + i * GTHREADS;
        int kr = s >> 4, j = s & 15;
        cp16(sB + (uint32_t)(kr * B_STRIDE + j * 16),
             Bg + (size_t)(k0 + kr) * Vn + j * 8);
    }
}

__global__ void __launch_bounds__(GTHREADS, 4)
gemm_ce_kernel(const float* __restrict__ be, const int* __restrict__ tgt32)
{
    extern __shared__ char smem[];
    const uint32_t sbase = s2u(smem);
    const uint32_t mbase = sbase + SM_MBAR;
    const int tid  = threadIdx.x;
    const int wid  = tid >> 5;
    const int lane = tid & 31;
    const int wm   = wid >> 1;
    const int wn   = wid & 1;

    const int vt = blockIdx.x, tt = blockIdx.y, b = blockIdx.z;
    const int e  = g_assign[b];
    const int v0 = vt * BN;
    const int t0 = tt * BM;

    const __half* Ag = g_Xh + ((size_t)b * Tn + t0) * Dn;
    const __half* Bg = g_Wh + (size_t)e * Dn * Vn + v0;

    if (tid == 0) {
        #pragma unroll
        for (int s = 0; s < NSTAGES; s++) {
            mbar_init(mbase + s * 16,     128);
            mbar_init(mbase + s * 16 + 8, 4);
        }
    }
    __syncthreads();

    uint32_t acc[4][8][2];
    #pragma unroll
    for (int mt = 0; mt < 4; mt++)
        #pragma unroll
        for (int nt = 0; nt < 8; nt++) { acc[mt][nt][0] = 0u; acc[mt][nt][1] = 0u; }

    const uint32_t a_lane_off = (uint32_t)((lane & 15) * A_STRIDE + (lane >> 4) * 16)
                              + (uint32_t)(wm * 64 * A_STRIDE);
    const uint32_t b_lane_off = (uint32_t)((lane & 15) * B_STRIDE
                              + (wn * 64 + (lane >> 4) * 8) * 2);

    uint32_t prod_ph = 7u;
    uint32_t cons_ph = 0u;

    #pragma unroll
    for (int k = 0; k < 2; k++) {
        mwait(mbase + k * 16 + 8, (prod_ph >> k) & 1u);
        prod_ph ^= (1u << k);
        load_stage(sbase + k * STAGE_BYTES, sbase + k * STAGE_BYTES + A_BYTES,
                   Ag, Bg, k * BK, tid);
        cpasync_arrive(mbase + k * 16);
    }

    const int NCHUNK = Dn / BK;   // 16
    int ps = 2, cs = 0;
    #pragma unroll 1
    for (int c = 0; c < NCHUNK; c++) {
        if (c + 2 < NCHUNK) {
            mwait(mbase + ps * 16 + 8, (prod_ph >> ps) & 1u);
            prod_ph ^= (1u << ps);
            load_stage(sbase + ps * STAGE_BYTES, sbase + ps * STAGE_BYTES + A_BYTES,
                       Ag, Bg, (c + 2) * BK, tid);
            cpasync_arrive(mbase + ps * 16);
            if (++ps == NSTAGES) ps = 0;
        }

        mwait(mbase + cs * 16, (cons_ph >> cs) & 1u);
        cons_ph ^= (1u << cs);

        const uint32_t aBase = sbase + cs * STAGE_BYTES + a_lane_off;
        const uint32_t bBase = sbase + cs * STAGE_BYTES + A_BYTES + b_lane_off;

        #pragma unroll
        for (int kt = 0; kt < 2; kt++) {
            uint32_t af[4][4], bf[16];
            #pragma unroll
            for (int mt = 0; mt < 4; mt++)
                ldsm_x4(af[mt][0], af[mt][1], af[mt][2], af[mt][3],
                        aBase + (uint32_t)(mt * 16 * A_STRIDE + kt * 32));
            #pragma unroll
            for (int g = 0; g < 4; g++)
                ldsm_x4t(bf[g * 4 + 0], bf[g * 4 + 1], bf[g * 4 + 2], bf[g * 4 + 3],
                         bBase + (uint32_t)(kt * 16 * B_STRIDE + g * 32));
            #pragma unroll
            for (int mt = 0; mt < 4; mt++)
                #pragma unroll
                for (int nt = 0; nt < 8; nt++)
                    mma_f16(acc[mt][nt], af[mt], &bf[nt * 2]);
        }

        __syncwarp();
        if (lane == 0) mbar_arrive(mbase + cs * 16 + 8);
        if (++cs == NSTAGES) cs = 0;
    }

    // ---- epilogue: t = logit*log2e in half2; exp via ex2.f16x2 ----
    const int c0 = (lane & 3) * 2;
    const int r0 = lane >> 2;
    const int vbase = v0 + wn * 64 + c0;
    const float* bias_base = be + (size_t)e * Vn + vbase;

    const __half2 l2e = __float2half2_rn(L2E);
    __half2 bsc[8];
    #pragma unroll
    for (int nt = 0; nt < 8; nt++)
        bsc[nt] = __floats2half2_rn(bias_base[nt * 8] * L2E, bias_base[nt * 8 + 1] * L2E);

    #pragma unroll
    for (int mt = 0; mt < 4; mt++) {
        const int row0 = t0 + wm * 64 + mt * 16 + r0;
        const int row1 = row0 + 8;
        const int d0 = tgt32[2 * (b * Tn + row0)] - vbase;
        const int d1 = tgt32[2 * (b * Tn + row1)] - vbase;
        float s0 = 0.0f, s1 = 0.0f;
        #pragma unroll
        for (int nt = 0; nt < 8; nt++) {
            __half2 a0 = *(__half2*)&acc[mt][nt][0];
            __half2 a1 = *(__half2*)&acc[mt][nt][1];
            __half2 t0h = __hfma2(a0, l2e, bsc[nt]);
            __half2 t1h = __hfma2(a1, l2e, bsc[nt]);
            float2 e0 = __half22float2(h2ex2(t0h));
            float2 e1 = __half22float2(h2ex2(t1h));
            s0 += e0.x + e0.y;
            s1 += e1.x + e1.y;
            if (d0 == nt * 8)     g_tgt[(size_t)b * Tn + row0] = __low2float(t0h);
            if (d0 == nt * 8 + 1) g_tgt[(size_t)b * Tn + row0] = __high2float(t0h);
            if (d1 == nt * 8)     g_tgt[(size_t)b * Tn + row1] = __low2float(t1h);
            if (d1 == nt * 8 + 1) g_tgt[(size_t)b * Tn + row1] = __high2float(t1h);
        }
        s0 += __shfl_xor_sync(0xffffffffu, s0, 1);
        s0 += __shfl_xor_sync(0xffffffffu, s0, 2);
        s1 += __shfl_xor_sync(0xffffffffu, s1, 1);
        s1 += __shfl_xor_sync(0xffffffffu, s1, 2);
        if ((lane & 3) == 0) {
            atomicAdd(&g_sumexp[(size_t)b * Tn + row0], s0);
            atomicAdd(&g_sumexp[(size_t)b * Tn + row1], s1);
        }
    }
}

// ---------------- CE reduce + final (last-block pattern) ----------------
__global__ void ce_final_kernel(float* __restrict__ out)
{
    const int b = blockIdx.x;
    const int tid = threadIdx.x;
    float s = 0.0f;
    for (int t = tid; t < Tn; t += NTHREADS) {
        const int idx = b * Tn + t;
        s += logf(g_sumexp[idx]) - g_tgt[idx] * LN2;   // g_tgt holds logit*log2e
    }
    __shared__ float red[NTHREADS];
    red[tid] = s;
    __syncthreads();
    for (int off = NTHREADS / 2; off > 0; off >>= 1) {
        if (tid < off) red[tid] += red[tid + off];
        __syncthreads();
    }
    __shared__ int last;
    if (tid == 0) {
        g_ce[b] = red[0] / (float)Tn;
        __threadfence();
        last = (atomicAdd(&g_cnt, 1) == Bn - 1);
    }
    __syncthreads();
    if (last && tid == 0) {
        float sums[En], cnt[En];
        #pragma unroll
        for (int e = 0; e < En; e++) { sums[e] = 0.0f; cnt[e] = 0.0f; }
        for (int bb = 0; bb < Bn; bb++) {
            sums[g_assign[bb]] += g_ce[bb];
            cnt[g_assign[bb]]  += 1.0f;
        }
        float tot = 0.0f;
        #pragma unroll
        for (int e = 0; e < En; e++)
            if (cnt[e] > 0.0f) tot += sums[e] / cnt[e];
        out[0] = tot;
    }
}

// ---------------- launcher ----------------
extern "C" void kernel_launch(void* const* d_in, const int* in_sizes, int n_in,
                              void* d_out, int out_size)
{
    const float* gate = (const float*)d_in[0];
    const float* X    = (const float*)d_in[1];
    const float* Wg   = (const float*)d_in[2];
    const float* bg   = (const float*)d_in[3];
    const float* We   = (const float*)d_in[4];
    const float* be   = (const float*)d_in[5];
    const int*   tgt  = (const int*)d_in[6];
    float* out = (float*)d_out;

    cudaFuncSetAttribute(gemm_ce_kernel, cudaFuncAttributeMaxDynamicSharedMemorySize, SMEM_BYTES);

    prep_kernel<<<NB_TOTAL, NTHREADS>>>((const float4*)X, (const float4*)We,
                                        gate, Wg, bg, out, out_size);

    dim3 grid(Vn / BN, Tn / BM, Bn);
    gemm_ce_kernel<<<grid, GTHREADS, SMEM_BYTES>>>(be, tgt);

    ce_final_kernel<<<Bn, NTHREADS>>>(out);
}

// round 14
// speedup vs baseline: 1.3175x; 1.0134x over previous
#include <cuda_runtime.h>
#include <cuda_fp16.h>
#include <math.h>
#include <stdint.h>

#define Bn 32
#define Tn 1024
#define Dn 512
#define Gn 256
#define En 8
#define Vn 8192

#define BM 128
#define BN 128
#define BK 32
#define GTHREADS 128
#define NTHREADS 256

#define L2E 1.4426950408889634f
#define LN2 0.6931471805599453f

// smem strides (bytes), padded for conflict-free ldmatrix
#define A_STRIDE 80      // 32 f16 = 64B + 16B pad
#define B_STRIDE 272     // 128 f16 = 256B + 16B pad
#define A_BYTES (BM * A_STRIDE)          // 10240
#define B_BYTES (BK * B_STRIDE)          // 8704
#define STAGE_BYTES (A_BYTES + B_BYTES)  // 18944
#define NSTAGES 3
#define SM_MBAR (NSTAGES * STAGE_BYTES)  // 56832
#define SMEM_BYTES (SM_MBAR + 64)        // 56896 per CTA, 4 CTAs/SM

// prep kernel block ranges (4 float4 per thread, MLP=4)
#define NB_Z 8              // zero g_sumexp: 32768 floats = 8192 float4 / (256*4)
#define NB_X 4096           // X: 4,194,304 float4 / (256*4)
#define NB_W 8192           // W: 8,388,608 float4 / (256*4)
#define NB_TOTAL (NB_Z + NB_X + NB_W + 1)

// ---------------- scratch (no cudaMalloc allowed) ----------------
__device__ __half g_Xh[(size_t)Bn * Tn * Dn];   // [B,T,D]
__device__ __half g_Wh[(size_t)En * Dn * Vn];   // [E,D,V]
__device__ float g_sumexp[Bn * Tn];
__device__ float g_tgt[Bn * Tn];                // stores logit * log2(e)
__device__ int   g_assign[Bn];
__device__ float g_ce[Bn];
__device__ int   g_cnt;

// ---------------- helpers ----------------
__device__ __forceinline__ uint32_t s2u(const void* p) {
    uint32_t a;
    asm("{ .reg .u64 t; cvta.to.shared.u64 t, %1; cvt.u32.u64 %0, t; }" : "=r"(a) : "l"(p));
    return a;
}
__device__ __forceinline__ void cp16(uint32_t dst, const void* src) {
    asm volatile("cp.async.cg.shared.global [%0], [%1], 16;" :: "r"(dst), "l"(src) : "memory");
}
__device__ __forceinline__ void mwait(uint32_t addr, uint32_t phase) {
    asm volatile(
        "{\n\t.reg .pred P;\n\t"
        "WL_%=:\n\t"
        "mbarrier.try_wait.parity.acquire.cta.shared::cta.b64 P, [%0], %1, 0x989680;\n\t"
        "@P bra WD_%=;\n\t"
        "bra WL_%=;\n\t"
        "WD_%=:\n\t}"
        :: "r"(addr), "r"(phase) : "memory");
}
__device__ __forceinline__ void mbar_init(uint32_t a, uint32_t cnt) {
    asm volatile("mbarrier.init.shared::cta.b64 [%0], %1;" :: "r"(a), "r"(cnt) : "memory");
}
__device__ __forceinline__ void mbar_arrive(uint32_t a) {
    asm volatile("mbarrier.arrive.shared::cta.b64 _, [%0];" :: "r"(a) : "memory");
}
__device__ __forceinline__ void cpasync_arrive(uint32_t a) {
    asm volatile("cp.async.mbarrier.arrive.noinc.shared::cta.b64 [%0];" :: "r"(a) : "memory");
}
__device__ __forceinline__ void ldsm_x4(uint32_t& r0, uint32_t& r1, uint32_t& r2, uint32_t& r3, uint32_t a) {
    asm volatile("ldmatrix.sync.aligned.m8n8.x4.shared.b16 {%0,%1,%2,%3}, [%4];"
                 : "=r"(r0), "=r"(r1), "=r"(r2), "=r"(r3) : "r"(a));
}
__device__ __forceinline__ void ldsm_x4t(uint32_t& r0, uint32_t& r1, uint32_t& r2, uint32_t& r3, uint32_t a) {
    asm volatile("ldmatrix.sync.aligned.m8n8.x4.trans.shared.b16 {%0,%1,%2,%3}, [%4];"
                 : "=r"(r0), "=r"(r1), "=r"(r2), "=r"(r3) : "r"(a));
}
__device__ __forceinline__ void mma_f16(uint32_t* d, const uint32_t* a, const uint32_t* b) {
    asm volatile("mma.sync.aligned.m16n8k16.row.col.f16.f16.f16.f16 "
                 "{%0,%1}, {%2,%3,%4,%5}, {%6,%7}, {%0,%1};"
                 : "+r"(d[0]), "+r"(d[1])
                 : "r"(a[0]), "r"(a[1]), "r"(a[2]), "r"(a[3]), "r"(b[0]), "r"(b[1]));
}
__device__ __forceinline__ __half2 h2ex2(__half2 x) {
    __half2 r;
    asm("ex2.approx.f16x2 %0, %1;" : "=r"(*(uint32_t*)&r) : "r"(*(uint32_t*)&x));
    return r;
}

// ---------------- prep: converts + zeroing + router, one kernel, MLP=4 ----------------
__global__ void prep_kernel(const float4* __restrict__ X,
                            const float4* __restrict__ W,
                            const float* __restrict__ gate,
                            const float* __restrict__ Wg,
                            const float* __restrict__ bg,
                            float* __restrict__ out, int out_size)
{
    const int bid = blockIdx.x;
    const int tid = threadIdx.x;

    if (bid < NB_Z) {
        size_t base = (size_t)bid * 256 + tid;
        const size_t stride = (size_t)NB_Z * 256;
        float4 z = make_float4(0.f, 0.f, 0.f, 0.f);
        #pragma unroll
        for (int k = 0; k < 4; k++)
            ((float4*)g_sumexp)[base + k * stride] = z;
        return;
    }
    if (bid < NB_Z + NB_X) {
        size_t base = (size_t)(bid - NB_Z) * 256 + tid;
        const size_t stride = (size_t)NB_X * 256;
        float4 v[4];
        #pragma unroll
        for (int k = 0; k < 4; k++) v[k] = X[base + k * stride];   // MLP=4
        __half2* o = (__half2*)g_Xh;
        #pragma unroll
        for (int k = 0; k < 4; k++) {
            size_t i = base + k * stride;
            o[2 * i + 0] = __floats2half2_rn(v[k].x, v[k].y);
            o[2 * i + 1] = __floats2half2_rn(v[k].z, v[k].w);
        }
        return;
    }
    if (bid < NB_Z + NB_X + NB_W) {
        size_t base = (size_t)(bid - NB_Z - NB_X) * 256 + tid;
        const size_t stride = (size_t)NB_W * 256;
        float4 v[4];
        #pragma unroll
        for (int k = 0; k < 4; k++) v[k] = W[base + k * stride];   // MLP=4
        __half2* o = (__half2*)g_Wh;
        #pragma unroll
        for (int k = 0; k < 4; k++) {
            size_t i = base + k * stride;
            o[2 * i + 0] = __floats2half2_rn(v[k].x, v[k].y);
            o[2 * i + 1] = __floats2half2_rn(v[k].z, v[k].w);
        }
        return;
    }

    // ---- router block ----
    for (int i = tid; i < out_size; i += NTHREADS) out[i] = 0.0f;
    if (tid == 0) g_cnt = 0;

    __shared__ float logits[Bn][En];
    int i = tid / En, j = tid % En;
    float acc = bg[j];
    const float* grow = gate + i * Gn;
    #pragma unroll 4
    for (int g = 0; g < Gn; g++) acc += grow[g] * Wg[g * En + j];
    logits[i][j] = acc;
    __syncthreads();

    if (tid < Bn) {
        float mx = logits[tid][0];
        int am = 0;
        #pragma unroll
        for (int e = 1; e < En; e++) {
            float v = logits[tid][e];
            if (v > mx) { mx = v; am = e; }
        }
        float ex[En], s = 0.0f;
        #pragma unroll
        for (int e = 0; e < En; e++) { ex[e] = expf(logits[tid][e] - mx); s += ex[e]; }
        float inv = 1.0f / s;
        #pragma unroll
        for (int e = 0; e < En; e++) out[1 + Bn + tid * En + e] = ex[e] * inv;
        out[1 + tid] = (float)am;
        g_assign[tid] = am;
    }
}

// ---------------- fused HMMA GEMM + CE epilogue (R10 shape, unchanged) ----------------
__device__ __forceinline__ void load_stage(uint32_t sA, uint32_t sB,
                                           const __half* Ag,
                                           const __half* Bg,
                                           int k0, int tid)
{
    #pragma unroll
    for (int i = 0; i < 4; i++) {
        int s = tid + i * GTHREADS;
        int row = s >> 2, j = s & 3;
        cp16(sA + (uint32_t)(row * A_STRIDE + j * 16),
             Ag + (size_t)row * Dn + k0 + j * 8);
    }
    #pragma unroll
    for (int i = 0; i < 4; i++) {
        int s = tid + i * GTHREADS;
        int kr = s >> 4, j = s & 15;
        cp16(sB + (uint32_t)(kr * B_STRIDE + j * 16),
             Bg + (size_t)(k0 + kr) * Vn + j * 8);
    }
}

__global__ void __launch_bounds__(GTHREADS, 4)
gemm_ce_kernel(const float* __restrict__ be, const int* __restrict__ tgt32)
{
    extern __shared__ char smem[];
    const uint32_t sbase = s2u(smem);
    const uint32_t mbase = sbase + SM_MBAR;
    const int tid  = threadIdx.x;
    const int wid  = tid >> 5;
    const int lane = tid & 31;
    const int wm   = wid >> 1;
    const int wn   = wid & 1;

    const int vt = blockIdx.x, tt = blockIdx.y, b = blockIdx.z;
    const int e  = g_assign[b];
    const int v0 = vt * BN;
    const int t0 = tt * BM;

    const __half* Ag = g_Xh + ((size_t)b * Tn + t0) * Dn;
    const __half* Bg = g_Wh + (size_t)e * Dn * Vn + v0;

    if (tid == 0) {
        #pragma unroll
        for (int s = 0; s < NSTAGES; s++) {
            mbar_init(mbase + s * 16,     128);
            mbar_init(mbase + s * 16 + 8, 4);
        }
    }
    __syncthreads();

    uint32_t acc[4][8][2];
    #pragma unroll
    for (int mt = 0; mt < 4; mt++)
        #pragma unroll
        for (int nt = 0; nt < 8; nt++) { acc[mt][nt][0] = 0u; acc[mt][nt][1] = 0u; }

    const uint32_t a_lane_off = (uint32_t)((lane & 15) * A_STRIDE + (lane >> 4) * 16)
                              + (uint32_t)(wm * 64 * A_STRIDE);
    const uint32_t b_lane_off = (uint32_t)((lane & 15) * B_STRIDE
                              + (wn * 64 + (lane >> 4) * 8) * 2);

    uint32_t prod_ph = 7u;
    uint32_t cons_ph = 0u;

    #pragma unroll
    for (int k = 0; k < 2; k++) {
        mwait(mbase + k * 16 + 8, (prod_ph >> k) & 1u);
        prod_ph ^= (1u << k);
        load_stage(sbase + k * STAGE_BYTES, sbase + k * STAGE_BYTES + A_BYTES,
                   Ag, Bg, k * BK, tid);
        cpasync_arrive(mbase + k * 16);
    }

    const int NCHUNK = Dn / BK;   // 16
    int ps = 2, cs = 0;
    #pragma unroll 1
    for (int c = 0; c < NCHUNK; c++) {
        if (c + 2 < NCHUNK) {
            mwait(mbase + ps * 16 + 8, (prod_ph >> ps) & 1u);
            prod_ph ^= (1u << ps);
            load_stage(sbase + ps * STAGE_BYTES, sbase + ps * STAGE_BYTES + A_BYTES,
                       Ag, Bg, (c + 2) * BK, tid);
            cpasync_arrive(mbase + ps * 16);
            if (++ps == NSTAGES) ps = 0;
        }

        mwait(mbase + cs * 16, (cons_ph >> cs) & 1u);
        cons_ph ^= (1u << cs);

        const uint32_t aBase = sbase + cs * STAGE_BYTES + a_lane_off;
        const uint32_t bBase = sbase + cs * STAGE_BYTES + A_BYTES + b_lane_off;

        #pragma unroll
        for (int kt = 0; kt < 2; kt++) {
            uint32_t af[4][4], bf[16];
            #pragma unroll
            for (int mt = 0; mt < 4; mt++)
                ldsm_x4(af[mt][0], af[mt][1], af[mt][2], af[mt][3],
                        aBase + (uint32_t)(mt * 16 * A_STRIDE + kt * 32));
            #pragma unroll
            for (int g = 0; g < 4; g++)
                ldsm_x4t(bf[g * 4 + 0], bf[g * 4 + 1], bf[g * 4 + 2], bf[g * 4 + 3],
                         bBase + (uint32_t)(kt * 16 * B_STRIDE + g * 32));
            #pragma unroll
            for (int mt = 0; mt < 4; mt++)
                #pragma unroll
                for (int nt = 0; nt < 8; nt++)
                    mma_f16(acc[mt][nt], af[mt], &bf[nt * 2]);
        }

        __syncwarp();
        if (lane == 0) mbar_arrive(mbase + cs * 16 + 8);
        if (++cs == NSTAGES) cs = 0;
    }

    // ---- epilogue ----
    const int c0 = (lane & 3) * 2;
    const int r0 = lane >> 2;
    const int vbase = v0 + wn * 64 + c0;
    const float* bias_base = be + (size_t)e * Vn + vbase;

    const __half2 l2e = __float2half2_rn(L2E);
    __half2 bsc[8];
    #pragma unroll
    for (int nt = 0; nt < 8; nt++)
        bsc[nt] = __floats2half2_rn(bias_base[nt * 8] * L2E, bias_base[nt * 8 + 1] * L2E);

    #pragma unroll
    for (int mt = 0; mt < 4; mt++) {
        const int row0 = t0 + wm * 64 + mt * 16 + r0;
        const int row1 = row0 + 8;
        const int d0 = tgt32[2 * (b * Tn + row0)] - vbase;
        const int d1 = tgt32[2 * (b * Tn + row1)] - vbase;
        float s0 = 0.0f, s1 = 0.0f;
        #pragma unroll
        for (int nt = 0; nt < 8; nt++) {
            __half2 a0 = *(__half2*)&acc[mt][nt][0];
            __half2 a1 = *(__half2*)&acc[mt][nt][1];
            __half2 t0h = __hfma2(a0, l2e, bsc[nt]);
            __half2 t1h = __hfma2(a1, l2e, bsc[nt]);
            float2 e0 = __half22float2(h2ex2(t0h));
            float2 e1 = __half22float2(h2ex2(t1h));
            s0 += e0.x + e0.y;
            s1 += e1.x + e1.y;
            if (d0 == nt * 8)     g_tgt[(size_t)b * Tn + row0] = __low2float(t0h);
            if (d0 == nt * 8 + 1) g_tgt[(size_t)b * Tn + row0] = __high2float(t0h);
            if (d1 == nt * 8)     g_tgt[(size_t)b * Tn + row1] = __low2float(t1h);
            if (d1 == nt * 8 + 1) g_tgt[(size_t)b * Tn + row1] = __high2float(t1h);
        }
        s0 += __shfl_xor_sync(0xffffffffu, s0, 1);
        s0 += __shfl_xor_sync(0xffffffffu, s0, 2);
        s1 += __shfl_xor_sync(0xffffffffu, s1, 1);
        s1 += __shfl_xor_sync(0xffffffffu, s1, 2);
        if ((lane & 3) == 0) {
            atomicAdd(&g_sumexp[(size_t)b * Tn + row0], s0);
            atomicAdd(&g_sumexp[(size_t)b * Tn + row1], s1);
        }
    }
}

// ---------------- CE reduce + final (last-block pattern) ----------------
__global__ void ce_final_kernel(float* __restrict__ out)
{
    const int b = blockIdx.x;
    const int tid = threadIdx.x;
    float s = 0.0f;
    for (int t = tid; t < Tn; t += NTHREADS) {
        const int idx = b * Tn + t;
        s += logf(g_sumexp[idx]) - g_tgt[idx] * LN2;
    }
    __shared__ float red[NTHREADS];
    red[tid] = s;
    __syncthreads();
    for (int off = NTHREADS / 2; off > 0; off >>= 1) {
        if (tid < off) red[tid] += red[tid + off];
        __syncthreads();
    }
    __shared__ int last;
    if (tid == 0) {
        g_ce[b] = red[0] / (float)Tn;
        __threadfence();
        last = (atomicAdd(&g_cnt, 1) == Bn - 1);
    }
    __syncthreads();
    if (last && tid == 0) {
        float sums[En], cnt[En];
        #pragma unroll
        for (int e = 0; e < En; e++) { sums[e] = 0.0f; cnt[e] = 0.0f; }
        for (int bb = 0; bb < Bn; bb++) {
            sums[g_assign[bb]] += g_ce[bb];
            cnt[g_assign[bb]]  += 1.0f;
        }
        float tot = 0.0f;
        #pragma unroll
        for (int e = 0; e < En; e++)
            if (cnt[e] > 0.0f) tot += sums[e] / cnt[e];
        out[0] = tot;
    }
}

// ---------------- launcher ----------------
extern "C" void kernel_launch(void* const* d_in, const int* in_sizes, int n_in,
                              void* d_out, int out_size)
{
    const float* gate = (const float*)d_in[0];
    const float* X    = (const float*)d_in[1];
    const float* Wg   = (const float*)d_in[2];
    const float* bg   = (const float*)d_in[3];
    const float* We   = (const float*)d_in[4];
    const float* be   = (const float*)d_in[5];
    const int*   tgt  = (const int*)d_in[6];
    float* out = (float*)d_out;

    cudaFuncSetAttribute(gemm_ce_kernel, cudaFuncAttributeMaxDynamicSharedMemorySize, SMEM_BYTES);

    prep_kernel<<<NB_TOTAL, NTHREADS>>>((const float4*)X, (const float4*)We,
                                        gate, Wg, bg, out, out_size);

    dim3 grid(Vn / BN, Tn / BM, Bn);
    gemm_ce_kernel<<<grid, GTHREADS, SMEM_BYTES>>>(be, tgt);

    ce_final_kernel<<<Bn, NTHREADS>>>(out);
}

// round 15
// speedup vs baseline: 1.3177x; 1.0001x over previous
#include <cuda_runtime.h>
#include <cuda_fp16.h>
#include <math.h>
#include <stdint.h>

#define Bn 32
#define Tn 1024
#define Dn 512
#define Gn 256
#define En 8
#define Vn 8192

#define BM 128
#define BN 128
#define BK 32
#define GTHREADS 128
#define NTHREADS 256

#define L2E 1.4426950408889634f
#define LN2 0.6931471805599453f

// smem strides (bytes), padded for conflict-free ldmatrix
#define A_STRIDE 80      // 32 f16 = 64B + 16B pad
#define B_STRIDE 272     // 128 f16 = 256B + 16B pad
#define A_BYTES (BM * A_STRIDE)          // 10240
#define B_BYTES (BK * B_STRIDE)          // 8704
#define STAGE_BYTES (A_BYTES + B_BYTES)  // 18944
#define NSTAGES 3
#define SM_MBAR (NSTAGES * STAGE_BYTES)  // 56832
#define SMEM_BYTES (SM_MBAR + 64)        // 56896 per CTA, 4 CTAs/SM

// prep block ranges: each thread = 4 iters x (read 32B fp32, write 16B f16)
#define NB_Z 8              // zero g_sumexp: 8192 float4 / (256*4)
#define NB_X 2048           // X out: 2,097,152 f16-float4 / (256*4)
#define NB_W 4096           // W out: 4,194,304 f16-float4 / (256*4)
#define NB_TOTAL (NB_Z + NB_X + NB_W + 1)

// ---------------- scratch (no cudaMalloc allowed) ----------------
__device__ __half g_Xh[(size_t)Bn * Tn * Dn];   // [B,T,D]
__device__ __half g_Wh[(size_t)En * Dn * Vn];   // [E,D,V]
__device__ float g_sumexp[Bn * Tn];
__device__ float g_tgt[Bn * Tn];                // stores logit * log2(e)
__device__ int   g_assign[Bn];
__device__ float g_ce[Bn];
__device__ int   g_cnt;

// ---------------- helpers ----------------
__device__ __forceinline__ uint32_t s2u(const void* p) {
    uint32_t a;
    asm("{ .reg .u64 t; cvta.to.shared.u64 t, %1; cvt.u32.u64 %0, t; }" : "=r"(a) : "l"(p));
    return a;
}
__device__ __forceinline__ void cp16(uint32_t dst, const void* src) {
    asm volatile("cp.async.cg.shared.global [%0], [%1], 16;" :: "r"(dst), "l"(src) : "memory");
}
__device__ __forceinline__ void mwait(uint32_t addr, uint32_t phase) {
    asm volatile(
        "{\n\t.reg .pred P;\n\t"
        "WL_%=:\n\t"
        "mbarrier.try_wait.parity.acquire.cta.shared::cta.b64 P, [%0], %1, 0x989680;\n\t"
        "@P bra WD_%=;\n\t"
        "bra WL_%=;\n\t"
        "WD_%=:\n\t}"
        :: "r"(addr), "r"(phase) : "memory");
}
__device__ __forceinline__ void mbar_init(uint32_t a, uint32_t cnt) {
    asm volatile("mbarrier.init.shared::cta.b64 [%0], %1;" :: "r"(a), "r"(cnt) : "memory");
}
__device__ __forceinline__ void mbar_arrive(uint32_t a) {
    asm volatile("mbarrier.arrive.shared::cta.b64 _, [%0];" :: "r"(a) : "memory");
}
__device__ __forceinline__ void cpasync_arrive(uint32_t a) {
    asm volatile("cp.async.mbarrier.arrive.noinc.shared::cta.b64 [%0];" :: "r"(a) : "memory");
}
__device__ __forceinline__ void ldsm_x4(uint32_t& r0, uint32_t& r1, uint32_t& r2, uint32_t& r3, uint32_t a) {
    asm volatile("ldmatrix.sync.aligned.m8n8.x4.shared.b16 {%0,%1,%2,%3}, [%4];"
                 : "=r"(r0), "=r"(r1), "=r"(r2), "=r"(r3) : "r"(a));
}
__device__ __forceinline__ void ldsm_x4t(uint32_t& r0, uint32_t& r1, uint32_t& r2, uint32_t& r3, uint32_t a) {
    asm volatile("ldmatrix.sync.aligned.m8n8.x4.trans.shared.b16 {%0,%1,%2,%3}, [%4];"
                 : "=r"(r0), "=r"(r1), "=r"(r2), "=r"(r3) : "r"(a));
}
__device__ __forceinline__ void mma_f16(uint32_t* d, const uint32_t* a, const uint32_t* b) {
    asm volatile("mma.sync.aligned.m16n8k16.row.col.f16.f16.f16.f16 "
                 "{%0,%1}, {%2,%3,%4,%5}, {%6,%7}, {%0,%1};"
                 : "+r"(d[0]), "+r"(d[1])
                 : "r"(a[0]), "r"(a[1]), "r"(a[2]), "r"(a[3]), "r"(b[0]), "r"(b[1]));
}
__device__ __forceinline__ __half2 h2ex2(__half2 x) {
    __half2 r;
    asm("ex2.approx.f16x2 %0, %1;" : "=r"(*(uint32_t*)&r) : "r"(*(uint32_t*)&x));
    return r;
}
__device__ __forceinline__ uint32_t h2u(__half2 h) { return *(uint32_t*)&h; }

// ---------------- prep: converts + zeroing + router, MLP=8 reads, STG.128 writes ---
__global__ void prep_kernel(const float4* __restrict__ X,
                            const float4* __restrict__ W,
                            const float* __restrict__ gate,
                            const float* __restrict__ Wg,
                            const float* __restrict__ bg,
                            float* __restrict__ out, int out_size)
{
    const int bid = blockIdx.x;
    const int tid = threadIdx.x;

    if (bid < NB_Z) {
        size_t base = (size_t)bid * 256 + tid;
        const size_t stride = (size_t)NB_Z * 256;
        float4 z = make_float4(0.f, 0.f, 0.f, 0.f);
        #pragma unroll
        for (int k = 0; k < 4; k++)
            ((float4*)g_sumexp)[base + k * stride] = z;
        return;
    }
    if (bid < NB_Z + NB_X) {
        size_t base = (size_t)(bid - NB_Z) * 256 + tid;   // output float4 units
        const size_t stride = (size_t)NB_X * 256;
        float4 a[4], b[4];
        #pragma unroll
        for (int k = 0; k < 4; k++) {                      // 8 outstanding LDG.128
            size_t j = base + k * stride;
            a[k] = X[2 * j];
            b[k] = X[2 * j + 1];
        }
        uint4* o = (uint4*)g_Xh;
        #pragma unroll
        for (int k = 0; k < 4; k++) {
            uint4 u;
            u.x = h2u(__floats2half2_rn(a[k].x, a[k].y));
            u.y = h2u(__floats2half2_rn(a[k].z, a[k].w));
            u.z = h2u(__floats2half2_rn(b[k].x, b[k].y));
            u.w = h2u(__floats2half2_rn(b[k].z, b[k].w));
            o[base + k * stride] = u;                      // STG.128, lane-contiguous
        }
        return;
    }
    if (bid < NB_Z + NB_X + NB_W) {
        size_t base = (size_t)(bid - NB_Z - NB_X) * 256 + tid;
        const size_t stride = (size_t)NB_W * 256;
        float4 a[4], b[4];
        #pragma unroll
        for (int k = 0; k < 4; k++) {
            size_t j = base + k * stride;
            a[k] = W[2 * j];
            b[k] = W[2 * j + 1];
        }
        uint4* o = (uint4*)g_Wh;
        #pragma unroll
        for (int k = 0; k < 4; k++) {
            uint4 u;
            u.x = h2u(__floats2half2_rn(a[k].x, a[k].y));
            u.y = h2u(__floats2half2_rn(a[k].z, a[k].w));
            u.z = h2u(__floats2half2_rn(b[k].x, b[k].y));
            u.w = h2u(__floats2half2_rn(b[k].z, b[k].w));
            o[base + k * stride] = u;
        }
        return;
    }

    // ---- router block ----
    for (int i = tid; i < out_size; i += NTHREADS) out[i] = 0.0f;
    if (tid == 0) g_cnt = 0;

    __shared__ float logits[Bn][En];
    int i = tid / En, j = tid % En;
    float acc = bg[j];
    const float* grow = gate + i * Gn;
    #pragma unroll 4
    for (int g = 0; g < Gn; g++) acc += grow[g] * Wg[g * En + j];
    logits[i][j] = acc;
    __syncthreads();

    if (tid < Bn) {
        float mx = logits[tid][0];
        int am = 0;
        #pragma unroll
        for (int e = 1; e < En; e++) {
            float v = logits[tid][e];
            if (v > mx) { mx = v; am = e; }
        }
        float ex[En], s = 0.0f;
        #pragma unroll
        for (int e = 0; e < En; e++) { ex[e] = expf(logits[tid][e] - mx); s += ex[e]; }
        float inv = 1.0f / s;
        #pragma unroll
        for (int e = 0; e < En; e++) out[1 + Bn + tid * En + e] = ex[e] * inv;
        out[1 + tid] = (float)am;
        g_assign[tid] = am;
    }
}

// ---------------- fused HMMA GEMM + CE epilogue (R10 shape, unchanged) ----------------
__device__ __forceinline__ void load_stage(uint32_t sA, uint32_t sB,
                                           const __half* Ag,
                                           const __half* Bg,
                                           int k0, int tid)
{
    #pragma unroll
    for (int i = 0; i < 4; i++) {
        int s = tid + i * GTHREADS;
        int row = s >> 2, j = s & 3;
        cp16(sA + (uint32_t)(row * A_STRIDE + j * 16),
             Ag + (size_t)row * Dn + k0 + j * 8);
    }
    #pragma unroll
    for (int i = 0; i < 4; i++) {
        int s = tid + i * GTHREADS;
        int kr = s >> 4, j = s & 15;
        cp16(sB + (uint32_t)(kr * B_STRIDE + j * 16),
             Bg + (size_t)(k0 + kr) * Vn + j * 8);
    }
}

__global__ void __launch_bounds__(GTHREADS, 4)
gemm_ce_kernel(const float* __restrict__ be, const int* __restrict__ tgt32)
{
    extern __shared__ char smem[];
    const uint32_t sbase = s2u(smem);
    const uint32_t mbase = sbase + SM_MBAR;
    const int tid  = threadIdx.x;
    const int wid  = tid >> 5;
    const int lane = tid & 31;
    const int wm   = wid >> 1;
    const int wn   = wid & 1;

    const int vt = blockIdx.x, tt = blockIdx.y, b = blockIdx.z;
    const int e  = g_assign[b];
    const int v0 = vt * BN;
    const int t0 = tt * BM;

    const __half* Ag = g_Xh + ((size_t)b * Tn + t0) * Dn;
    const __half* Bg = g_Wh + (size_t)e * Dn * Vn + v0;

    if (tid == 0) {
        #pragma unroll
        for (int s = 0; s < NSTAGES; s++) {
            mbar_init(mbase + s * 16,     128);
            mbar_init(mbase + s * 16 + 8, 4);
        }
    }
    __syncthreads();

    uint32_t acc[4][8][2];
    #pragma unroll
    for (int mt = 0; mt < 4; mt++)
        #pragma unroll
        for (int nt = 0; nt < 8; nt++) { acc[mt][nt][0] = 0u; acc[mt][nt][1] = 0u; }

    const uint32_t a_lane_off = (uint32_t)((lane & 15) * A_STRIDE + (lane >> 4) * 16)
                              + (uint32_t)(wm * 64 * A_STRIDE);
    const uint32_t b_lane_off = (uint32_t)((lane & 15) * B_STRIDE
                              + (wn * 64 + (lane >> 4) * 8) * 2);

    uint32_t prod_ph = 7u;
    uint32_t cons_ph = 0u;

    #pragma unroll
    for (int k = 0; k < 2; k++) {
        mwait(mbase + k * 16 + 8, (prod_ph >> k) & 1u);
        prod_ph ^= (1u << k);
        load_stage(sbase + k * STAGE_BYTES, sbase + k * STAGE_BYTES + A_BYTES,
                   Ag, Bg, k * BK, tid);
        cpasync_arrive(mbase + k * 16);
    }

    const int NCHUNK = Dn / BK;   // 16
    int ps = 2, cs = 0;
    #pragma unroll 1
    for (int c = 0; c < NCHUNK; c++) {
        if (c + 2 < NCHUNK) {
            mwait(mbase + ps * 16 + 8, (prod_ph >> ps) & 1u);
            prod_ph ^= (1u << ps);
            load_stage(sbase + ps * STAGE_BYTES, sbase + ps * STAGE_BYTES + A_BYTES,
                       Ag, Bg, (c + 2) * BK, tid);
            cpasync_arrive(mbase + ps * 16);
            if (++ps == NSTAGES) ps = 0;
        }

        mwait(mbase + cs * 16, (cons_ph >> cs) & 1u);
        cons_ph ^= (1u << cs);

        const uint32_t aBase = sbase + cs * STAGE_BYTES + a_lane_off;
        const uint32_t bBase = sbase + cs * STAGE_BYTES + A_BYTES + b_lane_off;

        #pragma unroll
        for (int kt = 0; kt < 2; kt++) {
            uint32_t af[4][4], bf[16];
            #pragma unroll
            for (int mt = 0; mt < 4; mt++)
                ldsm_x4(af[mt][0], af[mt][1], af[mt][2], af[mt][3],
                        aBase + (uint32_t)(mt * 16 * A_STRIDE + kt * 32));
            #pragma unroll
            for (int g = 0; g < 4; g++)
                ldsm_x4t(bf[g * 4 + 0], bf[g * 4 + 1], bf[g * 4 + 2], bf[g * 4 + 3],
                         bBase + (uint32_t)(kt * 16 * B_STRIDE + g * 32));
            #pragma unroll
            for (int mt = 0; mt < 4; mt++)
                #pragma unroll
                for (int nt = 0; nt < 8; nt++)
                    mma_f16(acc[mt][nt], af[mt], &bf[nt * 2]);
        }

        __syncwarp();
        if (lane == 0) mbar_arrive(mbase + cs * 16 + 8);
        if (++cs == NSTAGES) cs = 0;
    }

    // ---- epilogue ----
    const int c0 = (lane & 3) * 2;
    const int r0 = lane >> 2;
    const int vbase = v0 + wn * 64 + c0;
    const float* bias_base = be + (size_t)e * Vn + vbase;

    const __half2 l2e = __float2half2_rn(L2E);
    __half2 bsc[8];
    #pragma unroll
    for (int nt = 0; nt < 8; nt++)
        bsc[nt] = __floats2half2_rn(bias_base[nt * 8] * L2E, bias_base[nt * 8 + 1] * L2E);

    #pragma unroll
    for (int mt = 0; mt < 4; mt++) {
        const int row0 = t0 + wm * 64 + mt * 16 + r0;
        const int row1 = row0 + 8;
        const int d0 = tgt32[2 * (b * Tn + row0)] - vbase;
        const int d1 = tgt32[2 * (b * Tn + row1)] - vbase;
        float s0 = 0.0f, s1 = 0.0f;
        #pragma unroll
        for (int nt = 0; nt < 8; nt++) {
            __half2 a0 = *(__half2*)&acc[mt][nt][0];
            __half2 a1 = *(__half2*)&acc[mt][nt][1];
            __half2 t0h = __hfma2(a0, l2e, bsc[nt]);
            __half2 t1h = __hfma2(a1, l2e, bsc[nt]);
            float2 e0 = __half22float2(h2ex2(t0h));
            float2 e1 = __half22float2(h2ex2(t1h));
            s0 += e0.x + e0.y;
            s1 += e1.x + e1.y;
            if (d0 == nt * 8)     g_tgt[(size_t)b * Tn + row0] = __low2float(t0h);
            if (d0 == nt * 8 + 1) g_tgt[(size_t)b * Tn + row0] = __high2float(t0h);
            if (d1 == nt * 8)     g_tgt[(size_t)b * Tn + row1] = __low2float(t1h);
            if (d1 == nt * 8 + 1) g_tgt[(size_t)b * Tn + row1] = __high2float(t1h);
        }
        s0 += __shfl_xor_sync(0xffffffffu, s0, 1);
        s0 += __shfl_xor_sync(0xffffffffu, s0, 2);
        s1 += __shfl_xor_sync(0xffffffffu, s1, 1);
        s1 += __shfl_xor_sync(0xffffffffu, s1, 2);
        if ((lane & 3) == 0) {
            atomicAdd(&g_sumexp[(size_t)b * Tn + row0], s0);
            atomicAdd(&g_sumexp[(size_t)b * Tn + row1], s1);
        }
    }
}

// ---------------- CE reduce + final (last-block pattern) ----------------
__global__ void ce_final_kernel(float* __restrict__ out)
{
    const int b = blockIdx.x;
    const int tid = threadIdx.x;
    float s = 0.0f;
    for (int t = tid; t < Tn; t += NTHREADS) {
        const int idx = b * Tn + t;
        s += logf(g_sumexp[idx]) - g_tgt[idx] * LN2;
    }
    __shared__ float red[NTHREADS];
    red[tid] = s;
    __syncthreads();
    for (int off = NTHREADS / 2; off > 0; off >>= 1) {
        if (tid < off) red[tid] += red[tid + off];
        __syncthreads();
    }
    __shared__ int last;
    if (tid == 0) {
        g_ce[b] = red[0] / (float)Tn;
        __threadfence();
        last = (atomicAdd(&g_cnt, 1) == Bn - 1);
    }
    __syncthreads();
    if (last && tid == 0) {
        float sums[En], cnt[En];
        #pragma unroll
        for (int e = 0; e < En; e++) { sums[e] = 0.0f; cnt[e] = 0.0f; }
        for (int bb = 0; bb < Bn; bb++) {
            sums[g_assign[bb]] += g_ce[bb];
            cnt[g_assign[bb]]  += 1.0f;
        }
        float tot = 0.0f;
        #pragma unroll
        for (int e = 0; e < En; e++)
            if (cnt[e] > 0.0f) tot += sums[e] / cnt[e];
        out[0] = tot;
    }
}

// ---------------- launcher ----------------
extern "C" void kernel_launch(void* const* d_in, const int* in_sizes, int n_in,
                              void* d_out, int out_size)
{
    const float* gate = (const float*)d_in[0];
    const float* X    = (const float*)d_in[1];
    const float* Wg   = (const float*)d_in[2];
    const float* bg   = (const float*)d_in[3];
    const float* We   = (const float*)d_in[4];
    const float* be   = (const float*)d_in[5];
    const int*   tgt  = (const int*)d_in[6];
    float* out = (float*)d_out;

    cudaFuncSetAttribute(gemm_ce_kernel, cudaFuncAttributeMaxDynamicSharedMemorySize, SMEM_BYTES);

    prep_kernel<<<NB_TOTAL, NTHREADS>>>((const float4*)X, (const float4*)We,
                                        gate, Wg, bg, out, out_size);

    dim3 grid(Vn / BN, Tn / BM, Bn);
    gemm_ce_kernel<<<grid, GTHREADS, SMEM_BYTES>>>(be, tgt);

    ce_final_kernel<<<Bn, NTHREADS>>>(out);
}